// round 2
// baseline (speedup 1.0000x reference)
#include <cuda_runtime.h>
#include <cstdint>

// LIF recurrence: T=64 sequential steps, B*N = 524288 independent lanes.
//   h = v + (x - v) * 0.5
//   s = (h >= 1) ? 1 : 0
//   v = s ? 0 : h
// Pure HBM stream: 134 MB in + 134 MB out.
// R2: float2 granularity (2x threads -> occ 39%->~86%) + depth-3 prefetch
// to keep the per-thread DRAM pipe full.

static constexpr int T = 64;

__global__ void __launch_bounds__(256) lif_kernel(const float2* __restrict__ x,
                                                  float2* __restrict__ out,
                                                  int lanes2)  // B*N/2 per timestep
{
    int i = blockIdx.x * blockDim.x + threadIdx.x;
    if (i >= lanes2) return;

    float2 v = make_float2(0.f, 0.f);

    // depth-3 software pipeline: 3 loads in flight per thread
    float2 x0 = x[i];
    float2 x1 = x[(size_t)lanes2 + i];
    float2 x2 = x[2 * (size_t)lanes2 + i];

    #pragma unroll 8
    for (int t = 0; t < T; ++t) {
        float2 xn = make_float2(0.f, 0.f);
        if (t + 3 < T) xn = x[(size_t)(t + 3) * lanes2 + i];

        float2 h, s;
        h.x = v.x + (x0.x - v.x) * 0.5f;
        h.y = v.y + (x0.y - v.y) * 0.5f;

        s.x = (h.x >= 1.0f) ? 1.0f : 0.0f;
        s.y = (h.y >= 1.0f) ? 1.0f : 0.0f;

        v.x = (h.x >= 1.0f) ? 0.0f : h.x;
        v.y = (h.y >= 1.0f) ? 0.0f : h.y;

        out[(size_t)t * lanes2 + i] = s;

        x0 = x1;
        x1 = x2;
        x2 = xn;
    }
}

extern "C" void kernel_launch(void* const* d_in, const int* in_sizes, int n_in,
                              void* d_out, int out_size)
{
    const float2* x = (const float2*)d_in[0];
    float2* out = (float2*)d_out;

    int total = in_sizes[0];          // T * B * N
    int lanes = total / T;            // 524288
    int lanes2 = lanes / 2;           // 262144

    int threads = 256;
    int blocks = (lanes2 + threads - 1) / threads;
    lif_kernel<<<blocks, threads>>>(x, out, lanes2);
}